// round 1
// baseline (speedup 1.0000x reference)
#include <cuda_runtime.h>
#include <cuda_bf16.h>
#include <cstdint>

// out[r][c] = in[2r+1][2c+1], in: 8192x8192 fp32, out: 4096x4096 fp32.
// Each thread: 2x float4 loads (32B, covering 8 input cols = 4 odd cols),
// 1x float4 store (16B). Fully coalesced both directions.

#define N_IN  8192
#define N_OUT 4096

__global__ __launch_bounds__(256) void decimate2_kernel(
    const float4* __restrict__ in, float4* __restrict__ out)
{
    // total float4 outputs = N_OUT * (N_OUT/4) = 4096 * 1024
    const int idx  = blockIdx.x * blockDim.x + threadIdx.x;
    const int orow = idx >> 10;          // / 1024
    const int oc4  = idx & 1023;         // float4 index within output row

    // Input row 2*orow+1, as float4 pointer: row has 8192/4 = 2048 float4s.
    const float4* in_row = in + (size_t)(2 * orow + 1) * (N_IN / 4);

    // Output float4 covers output cols [4*oc4, 4*oc4+3]
    //   -> input odd cols 8*oc4+1, +3, +5, +7  -> input float4s 2*oc4, 2*oc4+1
    float4 a = in_row[2 * oc4];
    float4 b = in_row[2 * oc4 + 1];

    float4 r;
    r.x = a.y;  // col 8*oc4+1
    r.y = a.w;  // col 8*oc4+3
    r.z = b.y;  // col 8*oc4+5
    r.w = b.w;  // col 8*oc4+7

    out[(size_t)orow * (N_OUT / 4) + oc4] = r;
}

extern "C" void kernel_launch(void* const* d_in, const int* in_sizes, int n_in,
                              void* d_out, int out_size)
{
    const float4* in  = (const float4*)d_in[0];
    float4*       out = (float4*)d_out;

    const int total_f4 = N_OUT * (N_OUT / 4);   // 4,194,304
    decimate2_kernel<<<total_f4 / 256, 256>>>(in, out);
}

// round 2
// speedup vs baseline: 1.0749x; 1.0749x over previous
#include <cuda_runtime.h>
#include <cuda_bf16.h>
#include <cstdint>

// out[r][c] = in[2r+1][2c+1], in: 8192x8192 fp32, out: 4096x4096 fp32.
// One block per output row. Each thread produces 4 output float4s at
// blockDim stride; all 8 input float4 loads are front-batched (MLP=8),
// streaming cache hints (no reuse).

#define N_IN   8192
#define N_OUT  4096
#define F4_ROW (N_OUT / 4)   // 1024 output float4s per row
#define TPB    256
#define UNROLL 4             // F4_ROW / TPB

__global__ __launch_bounds__(TPB) void decimate2_kernel(
    const float4* __restrict__ in, float4* __restrict__ out)
{
    const int orow = blockIdx.x;
    const int tid  = threadIdx.x;

    const float4* in_row  = in  + (size_t)(2 * orow + 1) * (N_IN / 4);
    float4*       out_row = out + (size_t)orow * F4_ROW;

    float4 a[UNROLL], b[UNROLL];

    // Front-batched loads: 8 independent LDG.128 in flight per thread.
#pragma unroll
    for (int k = 0; k < UNROLL; k++) {
        const int oc4 = tid + k * TPB;
        a[k] = __ldcs(&in_row[2 * oc4]);
        b[k] = __ldcs(&in_row[2 * oc4 + 1]);
    }

#pragma unroll
    for (int k = 0; k < UNROLL; k++) {
        const int oc4 = tid + k * TPB;
        float4 r;
        r.x = a[k].y;   // odd col 8*oc4+1
        r.y = a[k].w;   // odd col 8*oc4+3
        r.z = b[k].y;   // odd col 8*oc4+5
        r.w = b[k].w;   // odd col 8*oc4+7
        __stcs(&out_row[oc4], r);
    }
}

extern "C" void kernel_launch(void* const* d_in, const int* in_sizes, int n_in,
                              void* d_out, int out_size)
{
    const float4* in  = (const float4*)d_in[0];
    float4*       out = (float4*)d_out;

    decimate2_kernel<<<N_OUT, TPB>>>(in, out);
}